// round 13
// baseline (speedup 1.0000x reference)
#include <cuda_runtime.h>
#include <cstdint>

#define W_IMG 512
#define H_IMG 512
#define HW    (512*512)
#define NB    4
#define EPS   1e-5f

#define TILE_W 64
#define TILE_H 8
#define BX 32
#define BY 8
#define NTHREADS (BX*BY)
#define PPT 2
#define HALO 2
#define SM_W (TILE_W + 2*HALO)   // 68
#define SM_H (TILE_H + 2*HALO)   // 12

// shared layout (floats, dynamic):
//   wbuf : [0, 12800)            25 taps x 8 rows x 64 cols
//   sf   : [12800, 13616)        12 x 68
//   sg   : [13616, 14432)
//   sh   : [14432, 15248)
#define WBUF_F4    3200           // 12800 floats as float4s
#define OFF_SF     12800
#define OFF_SG     13616
#define OFF_SH     14432
#define SMEM_FLOATS 15248
#define SMEM_BYTES  (SMEM_FLOATS * 4)   // 60992

#define NPROD 128                 // gray-max producer blocks (wave-1 resident)
#define CH_PB (NPROD / NB)        // 32 chunks per batch
#define NBLK_MAIN (NB * (H_IMG/TILE_H) * (W_IMG/TILE_W))    // 2048

// scratch (no device allocs) — counters reset by the electing last block each replay
__device__ float g_gmax_partial[NPROD];
__device__ int   g_count;
__device__ int   g_done;
__device__ float g_blockA[NBLK_MAIN];
__device__ float g_blockB[NBLK_MAIN];

__global__ __launch_bounds__(NTHREADS, 3)
void intensity_loss_main(const float* __restrict__ fake,
                         const float* __restrict__ gamma_hdr,
                         const float* __restrict__ hdr_im,
                         const float* __restrict__ r_weights,
                         const float* __restrict__ f_factors,
                         const float* __restrict__ gray,
                         float* __restrict__ out) {
    extern __shared__ __align__(16) float smem[];
    float* wbuf = smem;
    float* sf   = smem + OFF_SF;
    float* sg   = smem + OFF_SG;
    float* sh   = smem + OFF_SH;
    __shared__ float redA[BY], redB[BY];
    __shared__ float s_gmax;
    __shared__ int   s_last;

    const int b     = blockIdx.z;
    const int wbase = blockIdx.x * TILE_W;
    const int hbase = blockIdx.y * TILE_H;
    const int tx    = threadIdx.x;
    const int ty    = threadIdx.y;
    const int tid   = ty * BX + tx;
    const int lbid  = blockIdx.x + 8 * (blockIdx.y + 64 * blockIdx.z);

    // ---- FRONT-LOAD the entire weight tile (51.2KB) via cp.async:
    // all 25 tap-rows issued NOW, landing while graymax+staging run.
    {
        const float* rwbase = r_weights + (size_t)b * 25 * HW
                              + (size_t)hbase * W_IMG + wbase;
        const uint32_t wsm = (uint32_t)__cvta_generic_to_shared(wbuf);
        for (int q = tid; q < WBUF_F4; q += NTHREADS) {
            const int tap = q >> 7;          // 128 float4 per tap (8 rows x 16)
            const int rem = q & 127;
            const int row = rem >> 4;
            const int c4  = rem & 15;
            const float* src = rwbase + (size_t)tap * HW + row * W_IMG + c4 * 4;
            asm volatile("cp.async.cg.shared.global [%0], [%1], 16;"
                         :: "r"(wsm + q * 16), "l"(src));
        }
        asm volatile("cp.async.commit_group;" ::: "memory");
    }

    // ---- producer path: first NPROD blocks compute gray-max partials ----
    if (lbid < NPROD) {
        const int gb    = lbid / CH_PB;
        const int chunk = lbid - gb * CH_PB;
        const float4* p4 = reinterpret_cast<const float4*>(gray + (size_t)gb * HW);
        const int base = chunk * 2048;
        float m = 0.0f;
#pragma unroll
        for (int k = 0; k < 8; k++) {
            float4 v = p4[base + tid + k * 256];
            m = fmaxf(m, fmaxf(fmaxf(v.x, v.y), fmaxf(v.z, v.w)));
        }
#pragma unroll
        for (int o = 16; o > 0; o >>= 1)
            m = fmaxf(m, __shfl_down_sync(0xFFFFFFFFu, m, o));
        if ((tid & 31) == 0) redA[tid >> 5] = m;
        __syncthreads();
        if (tid == 0) {
            float mm = redA[0];
#pragma unroll
            for (int w = 1; w < BY; w++) mm = fmaxf(mm, redA[w]);
            g_gmax_partial[lbid] = mm;
            __threadfence();
            atomicAdd(&g_count, 1);
        }
        __syncthreads();   // redA reused later
    }

    const float ff   = f_factors[b];
    const float expo = 1.0f - ff;

    const float* fp = fake      + (size_t)b * HW;
    const float* gp = gamma_hdr + (size_t)b * HW;
    const float* hp = hdr_im    + (size_t)b * HW;

    // stage tile + halo (zero-pad OOB); hdr gets pow applied here
    for (int i = tid; i < SM_H * SM_W; i += NTHREADS) {
        const int r  = i / SM_W;
        const int c  = i - r * SM_W;
        const int ghh = hbase + r - HALO;
        const int gww = wbase + c - HALO;
        float vf = 0.0f, vg = 0.0f, vh = 0.0f;
        if (ghh >= 0 && ghh < H_IMG && gww >= 0 && gww < W_IMG) {
            const int gi = ghh * W_IMG + gww;
            vf = fp[gi];
            vg = gp[gi];
            vh = __powf(hp[gi], expo);
        }
        sf[i] = vf; sg[i] = vg; sh[i] = vh;
    }
    // all cp.async weights must have landed; then one barrier publishes
    // both the staged tiles and the weight buffer to every thread
    asm volatile("cp.async.wait_group 0;" ::: "memory");
    __syncthreads();

    const int lw = tx * PPT;
    const int lh = ty;

    float s1f[PPT] = {0,0}, s2f[PPT] = {0,0};
    float s1g[PPT] = {0,0}, s2g[PPT] = {0,0};
    float s1h[PPT] = {0,0}, ws [PPT] = {0,0};

    // ---- mainloop: ZERO global loads — weights and windows both in smem ----
    const float* wrow = wbuf + lh * 64 + lw;   // this thread's weight slot, tap 0
#pragma unroll
    for (int di = 0; di < 5; di++) {
        const int rowoff = (lh + di) * SM_W + lw;
        const float2 f0 = *reinterpret_cast<const float2*>(&sf[rowoff]);
        const float2 f1 = *reinterpret_cast<const float2*>(&sf[rowoff + 2]);
        const float2 f2 = *reinterpret_cast<const float2*>(&sf[rowoff + 4]);
        const float2 g0 = *reinterpret_cast<const float2*>(&sg[rowoff]);
        const float2 g1 = *reinterpret_cast<const float2*>(&sg[rowoff + 2]);
        const float2 g2 = *reinterpret_cast<const float2*>(&sg[rowoff + 4]);
        const float2 h0 = *reinterpret_cast<const float2*>(&sh[rowoff]);
        const float2 h1 = *reinterpret_cast<const float2*>(&sh[rowoff + 2]);
        const float2 h2 = *reinterpret_cast<const float2*>(&sh[rowoff + 4]);
        const float xf[6] = {f0.x, f0.y, f1.x, f1.y, f2.x, f2.y};
        const float xg[6] = {g0.x, g0.y, g1.x, g1.y, g2.x, g2.y};
        const float xh[6] = {h0.x, h0.y, h1.x, h1.y, h2.x, h2.y};

#pragma unroll
        for (int dj = 0; dj < 5; dj++) {
            // conflict-free LDS.64: lane stride 8B, consecutive
            const float2 wv = *reinterpret_cast<const float2*>(
                &wrow[(size_t)(di * 5 + dj) * 512]);
            const float rwa[PPT] = {wv.x, wv.y};
#pragma unroll
            for (int l = 0; l < PPT; l++) {
                const float w = rwa[l];
                ws[l] += w;
                const float a = xf[dj + l];
                const float wa = w * a;
                s1f[l] += wa;
                s2f[l] = fmaf(wa, a, s2f[l]);
                const float gq = xg[dj + l];
                const float wg = w * gq;
                s1g[l] += wg;
                s2g[l] = fmaf(wg, gq, s2g[l]);
                s1h[l] = fmaf(w, xh[dj + l], s1h[l]);
            }
        }
    }

    // ---- wait for gray-max producers (long since done), reduce per-batch ----
    if (tid == 0) {
        while (*(volatile int*)&g_count < NPROD) { }
    }
    __syncthreads();
    __threadfence();
    if (tid < 32) {
        float m = g_gmax_partial[b * CH_PB + tid];
#pragma unroll
        for (int o = 16; o > 0; o >>= 1)
            m = fmaxf(m, __shfl_down_sync(0xFFFFFFFFu, m, o));
        if (tid == 0) s_gmax = m;
    }
    __syncthreads();
    const float cobj = s_gmax / ff;   // ALPHA = 1

    // ---- epilogue: per-pixel scalar math ----
    float accA = 0.0f, accB = 0.0f;
#pragma unroll
    for (int l = 0; l < PPT; l++) {
        const float wsl  = ws[l];
        const float inv  = 1.0f / wsl;
        const float muf  = s1f[l] * inv;
        const float vrf  = fmaxf(s2f[l] * inv - muf * muf, 0.0f);
        const float stdf = sqrtf(vrf + EPS);
        const float mug  = s1g[l] * inv;
        const float vrg  = fmaxf(s2g[l] * inv - mug * mug, 0.0f);
        const float stdg = sqrtf(vrg + EPS);
        const float muh  = s1h[l] * inv;
        const float obj  = cobj * stdg * (muh + EPS);
        const float r    = 1.0f - stdf / (stdf + obj);
        const float wblf = wsl - 1.0f;
        accA = fmaf(r, wblf, accA);
        accB += wblf;
    }

    // block reduction -> per-block partials
#pragma unroll
    for (int o = 16; o > 0; o >>= 1) {
        accA += __shfl_down_sync(0xFFFFFFFFu, accA, o);
        accB += __shfl_down_sync(0xFFFFFFFFu, accB, o);
    }
    const int wid = tid >> 5, lane = tid & 31;
    if (lane == 0) { redA[wid] = accA; redB[wid] = accB; }
    __syncthreads();
    if (wid == 0) {
        accA = (lane < BY) ? redA[lane] : 0.0f;
        accB = (lane < BY) ? redB[lane] : 0.0f;
#pragma unroll
        for (int o = 4; o > 0; o >>= 1) {
            accA += __shfl_down_sync(0xFFFFFFFFu, accA, o);
            accB += __shfl_down_sync(0xFFFFFFFFu, accB, o);
        }
        if (lane == 0) {
            g_blockA[lbid] = accA;
            g_blockB[lbid] = accB;
        }
    }

    // ---- last-block-done election: single-kernel finalize ----
    __threadfence();
    if (tid == 0) s_last = atomicAdd(&g_done, 1);
    __syncthreads();
    if (s_last == NBLK_MAIN - 1) {
        float a = 0.0f, bsum = 0.0f;
#pragma unroll
        for (int kk = 0; kk < NBLK_MAIN / NTHREADS; kk++) {
            a    += g_blockA[tid + kk * NTHREADS];
            bsum += g_blockB[tid + kk * NTHREADS];
        }
#pragma unroll
        for (int o = 16; o > 0; o >>= 1) {
            a    += __shfl_down_sync(0xFFFFFFFFu, a, o);
            bsum += __shfl_down_sync(0xFFFFFFFFu, bsum, o);
        }
        if (lane == 0) { redA[wid] = a; redB[wid] = bsum; }
        __syncthreads();
        if (wid == 0) {
            a    = (lane < BY) ? redA[lane] : 0.0f;
            bsum = (lane < BY) ? redB[lane] : 0.0f;
#pragma unroll
            for (int o = 4; o > 0; o >>= 1) {
                a    += __shfl_down_sync(0xFFFFFFFFu, a, o);
                bsum += __shfl_down_sync(0xFFFFFFFFu, bsum, o);
            }
            if (lane == 0) {
                out[0] = a / bsum;
                g_done  = 0;
                g_count = 0;
            }
        }
    }
}

extern "C" void kernel_launch(void* const* d_in, const int* in_sizes, int n_in,
                              void* d_out, int out_size) {
    const float* fake      = (const float*)d_in[0];
    const float* gamma_hdr = (const float*)d_in[1];
    const float* hdr_im    = (const float*)d_in[2];
    const float* r_weights = (const float*)d_in[3];
    const float* f_factors = (const float*)d_in[4];
    const float* gray      = (const float*)d_in[5];
    float* out = (float*)d_out;

    static int smem_configured = 0;
    if (!smem_configured) {
        cudaFuncSetAttribute(intensity_loss_main,
                             cudaFuncAttributeMaxDynamicSharedMemorySize,
                             SMEM_BYTES);
        smem_configured = 1;
    }

    dim3 grid(W_IMG / TILE_W, H_IMG / TILE_H, NB);
    dim3 block(BX, BY);
    intensity_loss_main<<<grid, block, SMEM_BYTES>>>(fake, gamma_hdr, hdr_im,
                                                     r_weights, f_factors, gray, out);
}

// round 14
// speedup vs baseline: 1.4321x; 1.4321x over previous
#include <cuda_runtime.h>
#include <cstdint>

#define W_IMG 512
#define H_IMG 512
#define HW    (512*512)
#define NB    4
#define EPS   1e-5f

#define TILE_W 64
#define TILE_H 8
#define BX 32
#define BY 8
#define NTHREADS (BX*BY)
#define PPT 2
#define HALO 2
#define SM_W (TILE_W + 2*HALO)   // 68
#define SM_H (TILE_H + 2*HALO)   // 12

#define NCTA 512                  // persistent grid: all resident at occ 4 (<=592)
#define NPROD 128                 // gray-max producer CTAs (first 128, resident)
#define CH_PB (NPROD / NB)        // 32 chunks per batch

// scratch (no device allocs) — counters reset by the electing last block each replay
__device__ float g_gmax_partial[NPROD];
__device__ int   g_count;
__device__ int   g_done;
__device__ float g_blockA[NCTA];
__device__ float g_blockB[NCTA];

__global__ __launch_bounds__(NTHREADS, 4)
void intensity_loss_main(const float* __restrict__ fake,
                         const float* __restrict__ gamma_hdr,
                         const float* __restrict__ hdr_im,
                         const float* __restrict__ r_weights,
                         const float* __restrict__ f_factors,
                         const float* __restrict__ gray,
                         float* __restrict__ out) {
    __shared__ __align__(16) float sf[SM_H * SM_W];
    __shared__ __align__(16) float sg[SM_H * SM_W];
    __shared__ __align__(16) float sh[SM_H * SM_W];
    __shared__ float redA[BY], redB[BY];
    __shared__ float s_gmax4[NB];
    __shared__ int   s_last;

    const int cta   = blockIdx.x;
    const int bx    = cta & 7;           // 8 x-tiles
    const int by    = cta >> 3;          // 64 y-tiles
    const int wbase = bx * TILE_W;
    const int hbase = by * TILE_H;
    const int tx    = threadIdx.x;
    const int ty    = threadIdx.y;
    const int tid   = ty * BX + tx;

    // ---- producer phase: first NPROD CTAs compute gray-max partials once ----
    if (cta < NPROD) {
        const int gb    = cta / CH_PB;
        const int chunk = cta - gb * CH_PB;
        const float4* p4 = reinterpret_cast<const float4*>(gray + (size_t)gb * HW);
        const int base = chunk * 2048;
        float m = 0.0f;
#pragma unroll
        for (int k = 0; k < 8; k++) {
            float4 v = p4[base + tid + k * 256];
            m = fmaxf(m, fmaxf(fmaxf(v.x, v.y), fmaxf(v.z, v.w)));
        }
#pragma unroll
        for (int o = 16; o > 0; o >>= 1)
            m = fmaxf(m, __shfl_down_sync(0xFFFFFFFFu, m, o));
        if ((tid & 31) == 0) redA[tid >> 5] = m;
        __syncthreads();
        if (tid == 0) {
            float mm = redA[0];
#pragma unroll
            for (int w = 1; w < BY; w++) mm = fmaxf(mm, redA[w]);
            g_gmax_partial[cta] = mm;
            __threadfence();
            atomicAdd(&g_count, 1);
        }
        __syncthreads();   // redA reused later
    }

    const int lw = tx * PPT;
    const int lh = ty;

    float accA = 0.0f, accB = 0.0f;

    // ---- persistent tile loop: one tile per batch, same (bx,by) each time ----
#pragma unroll 1
    for (int t = 0; t < NB; t++) {
        if (t > 0) __syncthreads();      // previous tile fully consumed

        const float ff   = f_factors[t];
        const float expo = 1.0f - ff;
        const float* fp = fake      + (size_t)t * HW;
        const float* gp = gamma_hdr + (size_t)t * HW;
        const float* hp = hdr_im    + (size_t)t * HW;

        // stage tile + halo (zero-pad OOB); hdr gets pow applied here
        for (int i = tid; i < SM_H * SM_W; i += NTHREADS) {
            const int r  = i / SM_W;
            const int c  = i - r * SM_W;
            const int ghh = hbase + r - HALO;
            const int gww = wbase + c - HALO;
            float vf = 0.0f, vg = 0.0f, vh = 0.0f;
            if (ghh >= 0 && ghh < H_IMG && gww >= 0 && gww < W_IMG) {
                const int gi = ghh * W_IMG + gww;
                vf = fp[gi];
                vg = gp[gi];
                vh = __powf(hp[gi], expo);
            }
            sf[i] = vf; sg[i] = vg; sh[i] = vh;
        }
        __syncthreads();

        const float* rwp = r_weights + (size_t)t * 25 * HW
                           + (size_t)(hbase + lh) * W_IMG + (wbase + lw);

        float s1f[PPT] = {0,0}, s2f[PPT] = {0,0};
        float s1g[PPT] = {0,0}, s2g[PPT] = {0,0};
        float s1h[PPT] = {0,0}, ws [PPT] = {0,0};

#pragma unroll
        for (int di = 0; di < 5; di++) {
            float2 wv[5];
#pragma unroll
            for (int j = 0; j < 5; j++)
                wv[j] = *reinterpret_cast<const float2*>(rwp + (size_t)(di * 5 + j) * HW);

            const int rowoff = (lh + di) * SM_W + lw;
            const float2 f0 = *reinterpret_cast<const float2*>(&sf[rowoff]);
            const float2 f1 = *reinterpret_cast<const float2*>(&sf[rowoff + 2]);
            const float2 f2 = *reinterpret_cast<const float2*>(&sf[rowoff + 4]);
            const float2 g0 = *reinterpret_cast<const float2*>(&sg[rowoff]);
            const float2 g1 = *reinterpret_cast<const float2*>(&sg[rowoff + 2]);
            const float2 g2 = *reinterpret_cast<const float2*>(&sg[rowoff + 4]);
            const float2 h0 = *reinterpret_cast<const float2*>(&sh[rowoff]);
            const float2 h1 = *reinterpret_cast<const float2*>(&sh[rowoff + 2]);
            const float2 h2 = *reinterpret_cast<const float2*>(&sh[rowoff + 4]);
            const float xf[6] = {f0.x, f0.y, f1.x, f1.y, f2.x, f2.y};
            const float xg[6] = {g0.x, g0.y, g1.x, g1.y, g2.x, g2.y};
            const float xh[6] = {h0.x, h0.y, h1.x, h1.y, h2.x, h2.y};

#pragma unroll
            for (int dj = 0; dj < 5; dj++) {
                const float rwa[PPT] = {wv[dj].x, wv[dj].y};
#pragma unroll
                for (int l = 0; l < PPT; l++) {
                    const float w = rwa[l];
                    ws[l] += w;
                    const float a = xf[dj + l];
                    const float wa = w * a;
                    s1f[l] += wa;
                    s2f[l] = fmaf(wa, a, s2f[l]);
                    const float gq = xg[dj + l];
                    const float wg = w * gq;
                    s1g[l] += wg;
                    s2g[l] = fmaf(wg, gq, s2g[l]);
                    s1h[l] = fmaf(w, xh[dj + l], s1h[l]);
                }
            }
        }

        // first tile only: finish gray-max reduction for all batches
        if (t == 0) {
            if (tid == 0) {
                while (*(volatile int*)&g_count < NPROD) { }
            }
            __syncthreads();
            __threadfence();
            if (tid < 32) {
#pragma unroll
                for (int bb = 0; bb < NB; bb++) {
                    float m = g_gmax_partial[bb * CH_PB + tid];
#pragma unroll
                    for (int o = 16; o > 0; o >>= 1)
                        m = fmaxf(m, __shfl_down_sync(0xFFFFFFFFu, m, o));
                    if (tid == 0) s_gmax4[bb] = m;
                }
            }
            __syncthreads();
        }
        const float cobj = s_gmax4[t] / ff;   // ALPHA = 1

        // epilogue: per-pixel scalar math, accumulate across tiles
#pragma unroll
        for (int l = 0; l < PPT; l++) {
            const float wsl  = ws[l];
            const float inv  = 1.0f / wsl;
            const float muf  = s1f[l] * inv;
            const float vrf  = fmaxf(s2f[l] * inv - muf * muf, 0.0f);
            const float stdf = sqrtf(vrf + EPS);
            const float mug  = s1g[l] * inv;
            const float vrg  = fmaxf(s2g[l] * inv - mug * mug, 0.0f);
            const float stdg = sqrtf(vrg + EPS);
            const float muh  = s1h[l] * inv;
            const float obj  = cobj * stdg * (muh + EPS);
            const float r    = 1.0f - stdf / (stdf + obj);
            const float wblf = wsl - 1.0f;
            accA = fmaf(r, wblf, accA);
            accB += wblf;
        }
    }

    // ---- one block reduction for the whole CTA's 4 tiles ----
#pragma unroll
    for (int o = 16; o > 0; o >>= 1) {
        accA += __shfl_down_sync(0xFFFFFFFFu, accA, o);
        accB += __shfl_down_sync(0xFFFFFFFFu, accB, o);
    }
    const int wid = tid >> 5, lane = tid & 31;
    if (lane == 0) { redA[wid] = accA; redB[wid] = accB; }
    __syncthreads();
    if (wid == 0) {
        accA = (lane < BY) ? redA[lane] : 0.0f;
        accB = (lane < BY) ? redB[lane] : 0.0f;
#pragma unroll
        for (int o = 4; o > 0; o >>= 1) {
            accA += __shfl_down_sync(0xFFFFFFFFu, accA, o);
            accB += __shfl_down_sync(0xFFFFFFFFu, accB, o);
        }
        if (lane == 0) {
            g_blockA[cta] = accA;
            g_blockB[cta] = accB;
        }
    }

    // ---- last-block-done election: single-kernel finalize ----
    __threadfence();
    if (tid == 0) s_last = atomicAdd(&g_done, 1);
    __syncthreads();
    if (s_last == NCTA - 1) {
        float a = 0.0f, bsum = 0.0f;
#pragma unroll
        for (int kk = 0; kk < NCTA / NTHREADS; kk++) {
            a    += g_blockA[tid + kk * NTHREADS];
            bsum += g_blockB[tid + kk * NTHREADS];
        }
#pragma unroll
        for (int o = 16; o > 0; o >>= 1) {
            a    += __shfl_down_sync(0xFFFFFFFFu, a, o);
            bsum += __shfl_down_sync(0xFFFFFFFFu, bsum, o);
        }
        if (lane == 0) { redA[wid] = a; redB[wid] = bsum; }
        __syncthreads();
        if (wid == 0) {
            a    = (lane < BY) ? redA[lane] : 0.0f;
            bsum = (lane < BY) ? redB[lane] : 0.0f;
#pragma unroll
            for (int o = 4; o > 0; o >>= 1) {
                a    += __shfl_down_sync(0xFFFFFFFFu, a, o);
                bsum += __shfl_down_sync(0xFFFFFFFFu, bsum, o);
            }
            if (lane == 0) {
                out[0] = a / bsum;
                g_done  = 0;
                g_count = 0;
            }
        }
    }
}

extern "C" void kernel_launch(void* const* d_in, const int* in_sizes, int n_in,
                              void* d_out, int out_size) {
    const float* fake      = (const float*)d_in[0];
    const float* gamma_hdr = (const float*)d_in[1];
    const float* hdr_im    = (const float*)d_in[2];
    const float* r_weights = (const float*)d_in[3];
    const float* f_factors = (const float*)d_in[4];
    const float* gray      = (const float*)d_in[5];
    float* out = (float*)d_out;

    dim3 block(BX, BY);
    intensity_loss_main<<<NCTA, block>>>(fake, gamma_hdr, hdr_im,
                                         r_weights, f_factors, gray, out);
}